// round 9
// baseline (speedup 1.0000x reference)
#include <cuda_runtime.h>
#include <cstdint>
#include <cstddef>

#define N_NODES 50000
#define N_EDGES 800000
#define NB_SCAN 196          // ceil(50000/256)

// Scratch (device globals: no runtime allocation allowed)
__device__ __align__(16) float g_xw1[N_NODES * 64];   // x@W1[:64]+b1
__device__ __align__(16) float g_agg[N_NODES * 64];   // per-node sum of relu(h)
__device__ __align__(16) float g_wc[64 * 64];         // W2 @ W3[64:128,:]
__device__ float g_bc[64];                            // b2 @ W3[64:128,:]
__device__ int g_cnt[N_NODES];
__device__ int g_base[N_NODES];
__device__ int g_cursor[N_NODES];
__device__ int g_psrc[N_EDGES];                       // src, dst-sorted
__device__ int g_pe[N_EDGES];                         // edge id, dst-sorted
__device__ int g_bsum[NB_SCAN];
__device__ int g_boff[256];

typedef unsigned long long u64;

__device__ __forceinline__ u64 pack2(float v) {
    u64 r; asm("mov.b64 %0, {%1, %1};" : "=l"(r) : "f"(v)); return r;
}
__device__ __forceinline__ u64 pack2f(float lo, float hi) {
    u64 r; asm("mov.b64 %0, {%1, %2};" : "=l"(r) : "f"(lo), "f"(hi)); return r;
}
__device__ __forceinline__ void unpack2(u64 v, float &lo, float &hi) {
    asm("mov.b64 {%0, %1}, %2;" : "=f"(lo), "=f"(hi) : "l"(v));
}
__device__ __forceinline__ void ffma2(u64 &d, u64 a, u64 b) {
    asm("fma.rn.f32x2 %0, %1, %2, %0;" : "+l"(d) : "l"(a), "l"(b));
}

// ---------------------------------------------------------------------------
// K0: Wc = W2 @ W3[64:128,:],  bc = b2 @ W3[64:128,:]
// ---------------------------------------------------------------------------
__global__ void __launch_bounds__(64) prep_kernel(
        const float* __restrict__ W2,
        const float* __restrict__ W3,
        const float* __restrict__ b2) {
    __shared__ float sw2[64];
    int i = blockIdx.x, j = threadIdx.x;
    sw2[j] = W2[i * 64 + j];
    __syncthreads();
    float acc = 0.0f;
    #pragma unroll 8
    for (int k = 0; k < 64; k++)
        acc = fmaf(sw2[k], W3[(64 + k) * 64 + j], acc);
    g_wc[i * 64 + j] = acc;
    if (i == 0) {
        float accb = 0.0f;
        for (int k = 0; k < 64; k++)
            accb = fmaf(b2[k], W3[(64 + k) * 64 + j], accb);
        g_bc[j] = accb;
    }
}

// ---------------------------------------------------------------------------
// K1: g_xw1[n] = x[n] @ W1[0:64,:] + b1 ; zero g_cnt.
// ---------------------------------------------------------------------------
__global__ void __launch_bounds__(128) precompute_kernel(
        const float* __restrict__ x,
        const float* __restrict__ W1,
        const float* __restrict__ b1) {
    __shared__ ulonglong2 sW[64 * 16];   // 16 KB
    __shared__ ulonglong2 sb[16];
    int tid = threadIdx.x;
    const ulonglong2* W1v = reinterpret_cast<const ulonglong2*>(W1);
    for (int idx = tid; idx < 64 * 16; idx += 128) sW[idx] = W1v[idx];
    if (tid < 16) sb[tid] = reinterpret_cast<const ulonglong2*>(b1)[tid];
    __syncthreads();

    int n = blockIdx.x * 128 + tid;
    if (n >= N_NODES) return;

    u64 acc[32];
    #pragma unroll
    for (int j = 0; j < 16; j++) { ulonglong2 v = sb[j]; acc[2*j] = v.x; acc[2*j+1] = v.y; }

    const float4* xr = reinterpret_cast<const float4*>(x + (size_t)n * 64);
    #pragma unroll 1
    for (int c = 0; c < 2; c++) {
        float v[32];
        #pragma unroll
        for (int j = 0; j < 8; j++) {
            float4 f = xr[c * 8 + j];
            v[4*j] = f.x; v[4*j+1] = f.y; v[4*j+2] = f.z; v[4*j+3] = f.w;
        }
        #pragma unroll
        for (int i = 0; i < 32; i++) {
            u64 a = pack2(v[i]);
            #pragma unroll
            for (int j = 0; j < 16; j++) {
                ulonglong2 w = sW[(c * 32 + i) * 16 + j];
                ffma2(acc[2*j], a, w.x);
                ffma2(acc[2*j+1], a, w.y);
            }
        }
    }
    ulonglong2* o = reinterpret_cast<ulonglong2*>(g_xw1 + (size_t)n * 64);
    #pragma unroll
    for (int j = 0; j < 16; j++) {
        ulonglong2 v; v.x = acc[2*j]; v.y = acc[2*j+1]; o[j] = v;
    }
    g_cnt[n] = 0;
}

// ---------------------------------------------------------------------------
// K2: count in-degrees
// ---------------------------------------------------------------------------
__global__ void __launch_bounds__(256) count_kernel(const int* __restrict__ ei) {
    int e = blockIdx.x * 256 + threadIdx.x;
    atomicAdd(&g_cnt[ei[N_EDGES + e]], 1);
}

// ---------------------------------------------------------------------------
// K3a/b/c: two-level parallel exclusive scan of g_cnt -> g_base, g_cursor
// ---------------------------------------------------------------------------
__global__ void __launch_bounds__(256) scanA_kernel() {
    int b = blockIdx.x, tid = threadIdx.x;
    int idx = b * 256 + tid;
    int v = (idx < N_NODES) ? g_cnt[idx] : 0;
    __shared__ int ws[8];
    #pragma unroll
    for (int o = 16; o > 0; o >>= 1) v += __shfl_down_sync(0xffffffffu, v, o);
    if ((tid & 31) == 0) ws[tid >> 5] = v;
    __syncthreads();
    if (tid == 0) {
        int s = 0;
        #pragma unroll
        for (int k = 0; k < 8; k++) s += ws[k];
        g_bsum[b] = s;
    }
}

__global__ void __launch_bounds__(256) scanB_kernel() {
    int tid = threadIdx.x, lane = tid & 31, w = tid >> 5;
    int v = (tid < NB_SCAN) ? g_bsum[tid] : 0;
    int inc = v;
    __shared__ int ws[8];
    #pragma unroll
    for (int o = 1; o < 32; o <<= 1) {
        int t = __shfl_up_sync(0xffffffffu, inc, o);
        if (lane >= o) inc += t;
    }
    if (lane == 31) ws[w] = inc;
    __syncthreads();
    int off = 0;
    #pragma unroll
    for (int k = 0; k < 8; k++) off += (k < w) ? ws[k] : 0;
    g_boff[tid] = off + inc - v;   // exclusive
}

__global__ void __launch_bounds__(256) scanC_kernel() {
    int b = blockIdx.x, tid = threadIdx.x, lane = tid & 31, w = tid >> 5;
    int idx = b * 256 + tid;
    int c = (idx < N_NODES) ? g_cnt[idx] : 0;
    int inc = c;
    __shared__ int ws[8];
    #pragma unroll
    for (int o = 1; o < 32; o <<= 1) {
        int t = __shfl_up_sync(0xffffffffu, inc, o);
        if (lane >= o) inc += t;
    }
    if (lane == 31) ws[w] = inc;
    __syncthreads();
    int off = g_boff[b];
    #pragma unroll
    for (int k = 0; k < 8; k++) off += (k < w) ? ws[k] : 0;
    int base = off + inc - c;
    if (idx < N_NODES) { g_base[idx] = base; g_cursor[idx] = base; }
}

// ---------------------------------------------------------------------------
// K4: place edges into dst-sorted buckets (src + edge id only)
// ---------------------------------------------------------------------------
__global__ void __launch_bounds__(256) place_kernel(const int* __restrict__ ei) {
    int e = blockIdx.x * 256 + threadIdx.x;
    int d = ei[N_EDGES + e];
    int pos = atomicAdd(&g_cursor[d], 1);
    g_psrc[pos] = ei[e];
    g_pe[pos] = e;
}

// ---------------------------------------------------------------------------
// K5: aggregate, WARP PER NODE over its sorted bucket.
// Lane owns columns (2l, 2l+1); W1e slice in registers; per edge:
// coalesced xw1 row load + broadcast ef load + 16 FFMA2; relu-acc in regs;
// one plain store. No atomics, no smem staging. 1-deep prefetch pipeline.
// ---------------------------------------------------------------------------
__global__ void __launch_bounds__(256) aggregate_kernel(
        const float* __restrict__ ef,
        const float* __restrict__ W1) {
    int tid = threadIdx.x, warp = tid >> 5, lane = tid & 31;
    int n = blockIdx.x * 8 + warp;     // 6250 * 8 = 50000 exactly
    if (n >= N_NODES) return;

    // per-lane W1e slice: wreg[k] = (W1e[k][2*lane], W1e[k][2*lane+1])
    u64 wreg[16];
    #pragma unroll
    for (int k = 0; k < 16; k++) {
        float2 w = reinterpret_cast<const float2*>(W1 + (size_t)(64 + k) * 64)[lane];
        wreg[k] = pack2f(w.x, w.y);
    }

    int deg  = g_cnt[n];
    int base = g_base[n];

    float ax = 0.0f, ay = 0.0f;

    for (int c = 0; c < deg; c += 32) {
        int m = min(32, deg - c);
        int ps = 0, pev = 0;
        if (lane < m) {
            ps  = g_psrc[base + c + lane];
            pev = g_pe[base + c + lane];
        }
        // prologue: loads for i=0
        int src0 = __shfl_sync(0xffffffffu, ps, 0);
        int e0   = __shfl_sync(0xffffffffu, pev, 0);
        float2 xv = reinterpret_cast<const float2*>(g_xw1 + (size_t)src0 * 64)[lane];
        const float4* er = reinterpret_cast<const float4*>(ef + (size_t)e0 * 16);
        float4 f0 = er[0], f1 = er[1], f2 = er[2], f3 = er[3];

        for (int i = 0; i < m; i++) {
            // snapshot current edge data
            float2 cxv = xv;
            float4 c0 = f0, c1 = f1, c2 = f2, c3 = f3;
            // prefetch next edge (issues before the FMA chain below)
            if (i + 1 < m) {
                int s1 = __shfl_sync(0xffffffffu, ps, i + 1);
                int e1 = __shfl_sync(0xffffffffu, pev, i + 1);
                xv = reinterpret_cast<const float2*>(g_xw1 + (size_t)s1 * 64)[lane];
                const float4* er1 = reinterpret_cast<const float4*>(ef + (size_t)e1 * 16);
                f0 = er1[0]; f1 = er1[1]; f2 = er1[2]; f3 = er1[3];
            }
            // h = xw1[src] + ef @ W1e  (two independent chains)
            u64 acc0 = pack2f(cxv.x, cxv.y);
            u64 acc1 = 0ull;
            ffma2(acc0, pack2(c0.x), wreg[0]);  ffma2(acc1, pack2(c0.y), wreg[1]);
            ffma2(acc0, pack2(c0.z), wreg[2]);  ffma2(acc1, pack2(c0.w), wreg[3]);
            ffma2(acc0, pack2(c1.x), wreg[4]);  ffma2(acc1, pack2(c1.y), wreg[5]);
            ffma2(acc0, pack2(c1.z), wreg[6]);  ffma2(acc1, pack2(c1.w), wreg[7]);
            ffma2(acc0, pack2(c2.x), wreg[8]);  ffma2(acc1, pack2(c2.y), wreg[9]);
            ffma2(acc0, pack2(c2.z), wreg[10]); ffma2(acc1, pack2(c2.w), wreg[11]);
            ffma2(acc0, pack2(c3.x), wreg[12]); ffma2(acc1, pack2(c3.y), wreg[13]);
            ffma2(acc0, pack2(c3.z), wreg[14]); ffma2(acc1, pack2(c3.w), wreg[15]);
            float l0, h0, l1, h1;
            unpack2(acc0, l0, h0);
            unpack2(acc1, l1, h1);
            ax += fmaxf(l0 + l1, 0.0f);
            ay += fmaxf(h0 + h1, 0.0f);
        }
    }
    reinterpret_cast<float2*>(g_agg + (size_t)n * 64)[lane] = make_float2(ax, ay);
}

// ---------------------------------------------------------------------------
// K6: fused update+LN (nodeA folded via Wc/bc):
//   acc = x@W3[0:64] + (aggsum*inv)@Wc + b3 + bc*(cnt*inv)
//   y = relu(acc) + x ; LayerNorm -> out
// ---------------------------------------------------------------------------
__global__ void __launch_bounds__(128) nodeB_kernel(
        const float* __restrict__ x,
        const float* __restrict__ W3,
        const float* __restrict__ b3,
        const float* __restrict__ gamma,
        const float* __restrict__ beta,
        float* __restrict__ out) {
    __shared__ ulonglong2 sW[128 * 16];  // 32 KB
    __shared__ float sb3[64], sbc[64], sg[64], sbt[64];
    int tid = threadIdx.x;
    const ulonglong2* W3v = reinterpret_cast<const ulonglong2*>(W3);
    const ulonglong2* Wcv = reinterpret_cast<const ulonglong2*>(g_wc);
    for (int idx = tid; idx < 64 * 16; idx += 128) {
        sW[idx] = W3v[idx];
        sW[64 * 16 + idx] = Wcv[idx];
    }
    if (tid < 64) { sb3[tid] = b3[tid]; sbc[tid] = g_bc[tid]; sg[tid] = gamma[tid]; sbt[tid] = beta[tid]; }
    __syncthreads();

    int n = blockIdx.x * 128 + tid;
    if (n >= N_NODES) return;

    float cnt = (float)g_cnt[n];
    float inv = 1.0f / (cnt + 1e-8f);
    float bs  = cnt * inv;

    u64 acc[32];
    #pragma unroll
    for (int j = 0; j < 32; j++)
        acc[j] = pack2f(fmaf(bs, sbc[2*j], sb3[2*j]), fmaf(bs, sbc[2*j+1], sb3[2*j+1]));

    const float4* xr = reinterpret_cast<const float4*>(x + (size_t)n * 64);
    const float4* ar = reinterpret_cast<const float4*>(g_agg + (size_t)n * 64);

    #pragma unroll 1
    for (int c = 0; c < 4; c++) {
        bool isx = (c < 2);
        const float4* p = isx ? (xr + (c & 1) * 8) : (ar + (c & 1) * 8);
        float v[32];
        #pragma unroll
        for (int j = 0; j < 8; j++) {
            float4 f = p[j];
            v[4*j] = f.x; v[4*j+1] = f.y; v[4*j+2] = f.z; v[4*j+3] = f.w;
        }
        if (!isx) {
            #pragma unroll
            for (int j = 0; j < 32; j++) v[j] *= inv;
        }
        #pragma unroll
        for (int i = 0; i < 32; i++) {
            u64 a = pack2(v[i]);
            #pragma unroll
            for (int j = 0; j < 16; j++) {
                ulonglong2 w = sW[(c * 32 + i) * 16 + j];
                ffma2(acc[2*j], a, w.x);
                ffma2(acc[2*j+1], a, w.y);
            }
        }
    }

    float u[64];
    #pragma unroll
    for (int j = 0; j < 16; j++) {
        float4 f = xr[j];
        float a0, a1, a2, a3;
        unpack2(acc[2*j],   a0, a1);
        unpack2(acc[2*j+1], a2, a3);
        u[4*j]   = fmaxf(a0, 0.0f) + f.x;
        u[4*j+1] = fmaxf(a1, 0.0f) + f.y;
        u[4*j+2] = fmaxf(a2, 0.0f) + f.z;
        u[4*j+3] = fmaxf(a3, 0.0f) + f.w;
    }

    float s = 0.0f, ss = 0.0f;
    #pragma unroll
    for (int j = 0; j < 64; j++) { s += u[j]; ss = fmaf(u[j], u[j], ss); }
    float mu  = s * (1.0f / 64.0f);
    float var = ss * (1.0f / 64.0f) - mu * mu;
    float r   = rsqrtf(var + 1e-5f);

    float4* o = reinterpret_cast<float4*>(out + (size_t)n * 64);
    #pragma unroll
    for (int j = 0; j < 16; j++) {
        float4 v;
        v.x = (u[4*j]   - mu) * r * sg[4*j]   + sbt[4*j];
        v.y = (u[4*j+1] - mu) * r * sg[4*j+1] + sbt[4*j+1];
        v.z = (u[4*j+2] - mu) * r * sg[4*j+2] + sbt[4*j+2];
        v.w = (u[4*j+3] - mu) * r * sg[4*j+3] + sbt[4*j+3];
        o[j] = v;
    }
}

// ---------------------------------------------------------------------------
extern "C" void kernel_launch(void* const* d_in, const int* in_sizes, int n_in,
                              void* d_out, int out_size) {
    const float* x     = (const float*)d_in[0];
    const int*   ei    = (const int*)  d_in[1];
    const float* ef    = (const float*)d_in[2];
    const float* W1    = (const float*)d_in[3];
    const float* b1    = (const float*)d_in[4];
    const float* W2    = (const float*)d_in[5];
    const float* b2    = (const float*)d_in[6];
    const float* W3    = (const float*)d_in[7];
    const float* b3    = (const float*)d_in[8];
    const float* gamma = (const float*)d_in[9];
    const float* beta  = (const float*)d_in[10];
    float* out = (float*)d_out;

    (void)in_sizes; (void)n_in; (void)out_size;

    const int nb128 = (N_NODES + 127) / 128;

    prep_kernel<<<64, 64>>>(W2, W3, b2);
    precompute_kernel<<<nb128, 128>>>(x, W1, b1);
    count_kernel<<<N_EDGES / 256, 256>>>(ei);
    scanA_kernel<<<NB_SCAN, 256>>>();
    scanB_kernel<<<1, 256>>>();
    scanC_kernel<<<NB_SCAN, 256>>>();
    place_kernel<<<N_EDGES / 256, 256>>>(ei);
    aggregate_kernel<<<(N_NODES + 7) / 8, 256>>>(ef, W1);
    nodeB_kernel<<<nb128, 128>>>(x, W3, b3, gamma, beta, out);
}

// round 10
// speedup vs baseline: 1.2534x; 1.2534x over previous
#include <cuda_runtime.h>
#include <cstdint>
#include <cstddef>

#define N_NODES 50000
#define N_EDGES 800000
#define NB_SCAN 196          // ceil(50000/256)

// Scratch (device globals: no runtime allocation allowed)
__device__ __align__(16) float g_xw1[N_NODES * 64];   // x@W1[:64]+b1
__device__ __align__(16) float g_agg[N_NODES * 64];   // per-node sum of relu(h)
__device__ __align__(16) float g_wc[64 * 64];         // W2 @ W3[64:128,:]
__device__ float g_bc[64];                            // b2 @ W3[64:128,:]
__device__ int g_cnt[N_NODES];
__device__ int g_base[N_NODES];
__device__ int g_cursor[N_NODES];
__device__ int g_psrc[N_EDGES];                       // src, dst-sorted
__device__ int g_pe[N_EDGES];                         // edge id, dst-sorted
__device__ int g_pdst[N_EDGES];                       // dst, dst-sorted
__device__ int g_bsum[NB_SCAN];
__device__ int g_boff[256];

typedef unsigned long long u64;

__device__ __forceinline__ u64 pack2(float v) {
    u64 r; asm("mov.b64 %0, {%1, %1};" : "=l"(r) : "f"(v)); return r;
}
__device__ __forceinline__ u64 pack2f(float lo, float hi) {
    u64 r; asm("mov.b64 %0, {%1, %2};" : "=l"(r) : "f"(lo), "f"(hi)); return r;
}
__device__ __forceinline__ void unpack2(u64 v, float &lo, float &hi) {
    asm("mov.b64 {%0, %1}, %2;" : "=f"(lo), "=f"(hi) : "l"(v));
}
__device__ __forceinline__ void ffma2(u64 &d, u64 a, u64 b) {
    asm("fma.rn.f32x2 %0, %1, %2, %0;" : "+l"(d) : "l"(a), "l"(b));
}
__device__ __forceinline__ void red_add_v2(float* addr, float vx, float vy) {
    asm volatile("red.global.add.v2.f32 [%0], {%1, %2};"
                 :: "l"(addr), "f"(vx), "f"(vy) : "memory");
}

// ---------------------------------------------------------------------------
// K0: Wc = W2 @ W3[64:128,:],  bc = b2 @ W3[64:128,:]
// ---------------------------------------------------------------------------
__global__ void __launch_bounds__(64) prep_kernel(
        const float* __restrict__ W2,
        const float* __restrict__ W3,
        const float* __restrict__ b2) {
    __shared__ float sw2[64];
    int i = blockIdx.x, j = threadIdx.x;
    sw2[j] = W2[i * 64 + j];
    __syncthreads();
    float acc = 0.0f;
    #pragma unroll 8
    for (int k = 0; k < 64; k++)
        acc = fmaf(sw2[k], W3[(64 + k) * 64 + j], acc);
    g_wc[i * 64 + j] = acc;
    if (i == 0) {
        float accb = 0.0f;
        for (int k = 0; k < 64; k++)
            accb = fmaf(b2[k], W3[(64 + k) * 64 + j], accb);
        g_bc[j] = accb;
    }
}

// ---------------------------------------------------------------------------
// K1: g_xw1[n] = x[n] @ W1[0:64,:] + b1 ; zero g_agg row, g_cnt.
// ---------------------------------------------------------------------------
__global__ void __launch_bounds__(128) precompute_kernel(
        const float* __restrict__ x,
        const float* __restrict__ W1,
        const float* __restrict__ b1) {
    __shared__ ulonglong2 sW[64 * 16];   // 16 KB
    __shared__ ulonglong2 sb[16];
    int tid = threadIdx.x;
    const ulonglong2* W1v = reinterpret_cast<const ulonglong2*>(W1);
    for (int idx = tid; idx < 64 * 16; idx += 128) sW[idx] = W1v[idx];
    if (tid < 16) sb[tid] = reinterpret_cast<const ulonglong2*>(b1)[tid];
    __syncthreads();

    int n = blockIdx.x * 128 + tid;
    if (n >= N_NODES) return;

    u64 acc[32];
    #pragma unroll
    for (int j = 0; j < 16; j++) { ulonglong2 v = sb[j]; acc[2*j] = v.x; acc[2*j+1] = v.y; }

    const float4* xr = reinterpret_cast<const float4*>(x + (size_t)n * 64);
    #pragma unroll 1
    for (int c = 0; c < 2; c++) {
        float v[32];
        #pragma unroll
        for (int j = 0; j < 8; j++) {
            float4 f = xr[c * 8 + j];
            v[4*j] = f.x; v[4*j+1] = f.y; v[4*j+2] = f.z; v[4*j+3] = f.w;
        }
        #pragma unroll
        for (int i = 0; i < 32; i++) {
            u64 a = pack2(v[i]);
            #pragma unroll
            for (int j = 0; j < 16; j++) {
                ulonglong2 w = sW[(c * 32 + i) * 16 + j];
                ffma2(acc[2*j], a, w.x);
                ffma2(acc[2*j+1], a, w.y);
            }
        }
    }
    ulonglong2* o = reinterpret_cast<ulonglong2*>(g_xw1 + (size_t)n * 64);
    float4* az = reinterpret_cast<float4*>(g_agg + (size_t)n * 64);
    float4 z = make_float4(0.f, 0.f, 0.f, 0.f);
    #pragma unroll
    for (int j = 0; j < 16; j++) {
        ulonglong2 v; v.x = acc[2*j]; v.y = acc[2*j+1]; o[j] = v;
        az[j] = z;
    }
    g_cnt[n] = 0;
}

// ---------------------------------------------------------------------------
// K2: count in-degrees
// ---------------------------------------------------------------------------
__global__ void __launch_bounds__(256) count_kernel(const int* __restrict__ ei) {
    int e = blockIdx.x * 256 + threadIdx.x;
    atomicAdd(&g_cnt[ei[N_EDGES + e]], 1);
}

// ---------------------------------------------------------------------------
// K3a/b/c: two-level parallel exclusive scan of g_cnt -> g_base, g_cursor
// ---------------------------------------------------------------------------
__global__ void __launch_bounds__(256) scanA_kernel() {
    int b = blockIdx.x, tid = threadIdx.x;
    int idx = b * 256 + tid;
    int v = (idx < N_NODES) ? g_cnt[idx] : 0;
    __shared__ int ws[8];
    #pragma unroll
    for (int o = 16; o > 0; o >>= 1) v += __shfl_down_sync(0xffffffffu, v, o);
    if ((tid & 31) == 0) ws[tid >> 5] = v;
    __syncthreads();
    if (tid == 0) {
        int s = 0;
        #pragma unroll
        for (int k = 0; k < 8; k++) s += ws[k];
        g_bsum[b] = s;
    }
}

__global__ void __launch_bounds__(256) scanB_kernel() {
    int tid = threadIdx.x, lane = tid & 31, w = tid >> 5;
    int v = (tid < NB_SCAN) ? g_bsum[tid] : 0;
    int inc = v;
    __shared__ int ws[8];
    #pragma unroll
    for (int o = 1; o < 32; o <<= 1) {
        int t = __shfl_up_sync(0xffffffffu, inc, o);
        if (lane >= o) inc += t;
    }
    if (lane == 31) ws[w] = inc;
    __syncthreads();
    int off = 0;
    #pragma unroll
    for (int k = 0; k < 8; k++) off += (k < w) ? ws[k] : 0;
    g_boff[tid] = off + inc - v;   // exclusive
}

__global__ void __launch_bounds__(256) scanC_kernel() {
    int b = blockIdx.x, tid = threadIdx.x, lane = tid & 31, w = tid >> 5;
    int idx = b * 256 + tid;
    int c = (idx < N_NODES) ? g_cnt[idx] : 0;
    int inc = c;
    __shared__ int ws[8];
    #pragma unroll
    for (int o = 1; o < 32; o <<= 1) {
        int t = __shfl_up_sync(0xffffffffu, inc, o);
        if (lane >= o) inc += t;
    }
    if (lane == 31) ws[w] = inc;
    __syncthreads();
    int off = g_boff[b];
    #pragma unroll
    for (int k = 0; k < 8; k++) off += (k < w) ? ws[k] : 0;
    int base = off + inc - c;
    if (idx < N_NODES) { g_base[idx] = base; g_cursor[idx] = base; }
}

// ---------------------------------------------------------------------------
// K4: place edges into dst-sorted buckets
// ---------------------------------------------------------------------------
__global__ void __launch_bounds__(256) place_kernel(const int* __restrict__ ei) {
    int e = blockIdx.x * 256 + threadIdx.x;
    int d = ei[N_EDGES + e];
    int pos = atomicAdd(&g_cursor[d], 1);
    g_psrc[pos] = ei[e];
    g_pe[pos] = e;
    g_pdst[pos] = d;
}

// ---------------------------------------------------------------------------
// K5: aggregate over sorted slots. Block = 128 slots.
//   m = relu(xw1[src] + ef@W1e)  -> smem
//   warp-chunk reduce: warp w sweeps slots [32w,32w+32), lane owns col pair;
//   run breaks are warp-uniform -> red.add.v2 per run. No ballots, no heads.
// ---------------------------------------------------------------------------
__global__ void __launch_bounds__(128) aggregate_kernel(
        const float* __restrict__ ef,
        const float* __restrict__ W1) {
    __shared__ ulonglong2 sW1e[16 * 16];          // 4 KB
    __shared__ float sm[128 * 66];                // 33 KB, stride 66
    __shared__ int sdst[128];

    int tid = threadIdx.x;
    sW1e[tid * 2]     = reinterpret_cast<const ulonglong2*>(W1)[1024 + tid * 2];
    sW1e[tid * 2 + 1] = reinterpret_cast<const ulonglong2*>(W1)[1024 + tid * 2 + 1];

    int slot = blockIdx.x * 128 + tid;            // N_EDGES % 128 == 0
    int src = g_psrc[slot];
    int e   = g_pe[slot];
    int d   = g_pdst[slot];
    sdst[tid] = d;

    // message compute
    u64 acc[32];
    const ulonglong2* xr = reinterpret_cast<const ulonglong2*>(g_xw1 + (size_t)src * 64);
    #pragma unroll
    for (int j = 0; j < 16; j++) { ulonglong2 v = xr[j]; acc[2*j] = v.x; acc[2*j+1] = v.y; }

    float efr[16];
    const float4* er = reinterpret_cast<const float4*>(ef + (size_t)e * 16);
    #pragma unroll
    for (int j = 0; j < 4; j++) {
        float4 f = er[j];
        efr[4*j] = f.x; efr[4*j+1] = f.y; efr[4*j+2] = f.z; efr[4*j+3] = f.w;
    }
    __syncthreads();   // sW1e ready

    #pragma unroll
    for (int i = 0; i < 16; i++) {
        u64 a = pack2(efr[i]);
        #pragma unroll
        for (int j = 0; j < 16; j++) {
            ulonglong2 w = sW1e[i * 16 + j];
            ffma2(acc[2*j], a, w.x);
            ffma2(acc[2*j+1], a, w.y);
        }
    }

    // relu -> smem
    float2* myrow = reinterpret_cast<float2*>(sm + tid * 66);
    #pragma unroll
    for (int j = 0; j < 32; j++) {
        float lo, hi; unpack2(acc[j], lo, hi);
        myrow[j] = make_float2(fmaxf(lo, 0.f), fmaxf(hi, 0.f));
    }
    __syncthreads();   // messages + sdst visible

    // warp-chunk reduce: this warp handles its own 32 slots
    int warp = tid >> 5, lane = tid & 31;
    int s0 = warp * 32;
    float sx = 0.0f, sy = 0.0f;
    int dprev = sdst[s0];
    #pragma unroll 4
    for (int t = 0; t < 32; t++) {
        int dcur = sdst[s0 + t];                 // broadcast, warp-uniform
        if (dcur != dprev) {                     // warp-uniform branch
            red_add_v2(g_agg + (size_t)dprev * 64 + 2 * lane, sx, sy);
            sx = 0.0f; sy = 0.0f;
            dprev = dcur;
        }
        float2 v = *reinterpret_cast<const float2*>(sm + (s0 + t) * 66 + 2 * lane);
        sx += v.x; sy += v.y;
    }
    red_add_v2(g_agg + (size_t)dprev * 64 + 2 * lane, sx, sy);
}

// ---------------------------------------------------------------------------
// K6: fused update+LN (nodeA folded via Wc/bc), M=2 node blocking:
//   acc = x@W3[0:64] + (aggsum*inv)@Wc + b3 + bc*(cnt*inv)
//   y = relu(acc) + x ; LayerNorm -> out
// ---------------------------------------------------------------------------
__global__ void __launch_bounds__(128) nodeB_kernel(
        const float* __restrict__ x,
        const float* __restrict__ W3,
        const float* __restrict__ b3,
        const float* __restrict__ gamma,
        const float* __restrict__ beta,
        float* __restrict__ out) {
    __shared__ ulonglong2 sW[128 * 16];  // 32 KB: rows 0..63 W3 top, 64..127 Wc
    __shared__ float sb3[64], sbc[64], sg[64], sbt[64];
    int tid = threadIdx.x;
    const ulonglong2* W3v = reinterpret_cast<const ulonglong2*>(W3);
    const ulonglong2* Wcv = reinterpret_cast<const ulonglong2*>(g_wc);
    for (int idx = tid; idx < 64 * 16; idx += 128) {
        sW[idx] = W3v[idx];
        sW[64 * 16 + idx] = Wcv[idx];
    }
    if (tid < 64) { sb3[tid] = b3[tid]; sbc[tid] = g_bc[tid]; sg[tid] = gamma[tid]; sbt[tid] = beta[tid]; }
    __syncthreads();

    int n0 = blockIdx.x * 256 + tid;
    int n1 = n0 + 128;
    bool vA = (n0 < N_NODES), vB = (n1 < N_NODES);
    int nA = vA ? n0 : 0, nB = vB ? n1 : 0;

    float cntA = (float)g_cnt[nA];
    float cntB = (float)g_cnt[nB];
    float invA = 1.0f / (cntA + 1e-8f), invB = 1.0f / (cntB + 1e-8f);
    float bsA = cntA * invA, bsB = cntB * invB;

    u64 accA[32], accB[32];
    #pragma unroll
    for (int j = 0; j < 32; j++) {
        accA[j] = pack2f(fmaf(bsA, sbc[2*j], sb3[2*j]), fmaf(bsA, sbc[2*j+1], sb3[2*j+1]));
        accB[j] = pack2f(fmaf(bsB, sbc[2*j], sb3[2*j]), fmaf(bsB, sbc[2*j+1], sb3[2*j+1]));
    }

    const float4* xA = reinterpret_cast<const float4*>(x + (size_t)nA * 64);
    const float4* xB = reinterpret_cast<const float4*>(x + (size_t)nB * 64);
    const float4* aA = reinterpret_cast<const float4*>(g_agg + (size_t)nA * 64);
    const float4* aB = reinterpret_cast<const float4*>(g_agg + (size_t)nB * 64);

    #pragma unroll 1
    for (int c = 0; c < 8; c++) {
        bool isx = (c < 4);
        const float4* pA = isx ? (xA + c * 4) : (aA + (c - 4) * 4);
        const float4* pB = isx ? (xB + c * 4) : (aB + (c - 4) * 4);
        float va[16], vb[16];
        #pragma unroll
        for (int j = 0; j < 4; j++) {
            float4 fa = pA[j];
            float4 fb = pB[j];
            va[4*j] = fa.x; va[4*j+1] = fa.y; va[4*j+2] = fa.z; va[4*j+3] = fa.w;
            vb[4*j] = fb.x; vb[4*j+1] = fb.y; vb[4*j+2] = fb.z; vb[4*j+3] = fb.w;
        }
        if (!isx) {
            #pragma unroll
            for (int j = 0; j < 16; j++) { va[j] *= invA; vb[j] *= invB; }
        }
        #pragma unroll
        for (int i = 0; i < 16; i++) {
            u64 a0 = pack2(va[i]);
            u64 a1 = pack2(vb[i]);
            #pragma unroll
            for (int j = 0; j < 16; j++) {
                ulonglong2 w = sW[(c * 16 + i) * 16 + j];
                ffma2(accA[2*j], a0, w.x); ffma2(accA[2*j+1], a0, w.y);
                ffma2(accB[2*j], a1, w.x); ffma2(accB[2*j+1], a1, w.y);
            }
        }
    }

    // finalize node A then node B (reuse registers)
    #pragma unroll 1
    for (int m = 0; m < 2; m++) {
        bool valid = m ? vB : vA;
        if (!valid) continue;
        int n = m ? n1 : n0;
        u64* acc = m ? accB : accA;
        const float4* xr = reinterpret_cast<const float4*>(x + (size_t)n * 64);

        float u[64];
        #pragma unroll
        for (int j = 0; j < 16; j++) {
            float4 f = xr[j];
            float a0, a1, a2, a3;
            unpack2(acc[2*j],   a0, a1);
            unpack2(acc[2*j+1], a2, a3);
            u[4*j]   = fmaxf(a0, 0.0f) + f.x;
            u[4*j+1] = fmaxf(a1, 0.0f) + f.y;
            u[4*j+2] = fmaxf(a2, 0.0f) + f.z;
            u[4*j+3] = fmaxf(a3, 0.0f) + f.w;
        }
        float s = 0.0f, ss = 0.0f;
        #pragma unroll
        for (int j = 0; j < 64; j++) { s += u[j]; ss = fmaf(u[j], u[j], ss); }
        float mu  = s * (1.0f / 64.0f);
        float var = ss * (1.0f / 64.0f) - mu * mu;
        float r   = rsqrtf(var + 1e-5f);

        float4* o = reinterpret_cast<float4*>(out + (size_t)n * 64);
        #pragma unroll
        for (int j = 0; j < 16; j++) {
            float4 v;
            v.x = (u[4*j]   - mu) * r * sg[4*j]   + sbt[4*j];
            v.y = (u[4*j+1] - mu) * r * sg[4*j+1] + sbt[4*j+1];
            v.z = (u[4*j+2] - mu) * r * sg[4*j+2] + sbt[4*j+2];
            v.w = (u[4*j+3] - mu) * r * sg[4*j+3] + sbt[4*j+3];
            o[j] = v;
        }
    }
}

// ---------------------------------------------------------------------------
extern "C" void kernel_launch(void* const* d_in, const int* in_sizes, int n_in,
                              void* d_out, int out_size) {
    const float* x     = (const float*)d_in[0];
    const int*   ei    = (const int*)  d_in[1];
    const float* ef    = (const float*)d_in[2];
    const float* W1    = (const float*)d_in[3];
    const float* b1    = (const float*)d_in[4];
    const float* W2    = (const float*)d_in[5];
    const float* b2    = (const float*)d_in[6];
    const float* W3    = (const float*)d_in[7];
    const float* b3    = (const float*)d_in[8];
    const float* gamma = (const float*)d_in[9];
    const float* beta  = (const float*)d_in[10];
    float* out = (float*)d_out;

    (void)in_sizes; (void)n_in; (void)out_size;

    const int nb128 = (N_NODES + 127) / 128;
    const int nb256 = (N_NODES + 255) / 256;

    prep_kernel<<<64, 64>>>(W2, W3, b2);
    precompute_kernel<<<nb128, 128>>>(x, W1, b1);
    count_kernel<<<N_EDGES / 256, 256>>>(ei);
    scanA_kernel<<<NB_SCAN, 256>>>();
    scanB_kernel<<<1, 256>>>();
    scanC_kernel<<<NB_SCAN, 256>>>();
    place_kernel<<<N_EDGES / 256, 256>>>(ei);
    aggregate_kernel<<<N_EDGES / 128, 128>>>(ef, W1);
    nodeB_kernel<<<nb256, 128>>>(x, W3, b3, gamma, beta, out);
}

// round 11
// speedup vs baseline: 1.3690x; 1.0922x over previous
#include <cuda_runtime.h>
#include <cstdint>
#include <cstddef>

#define N_NODES 50000
#define N_EDGES 800000
#define NB_SCAN 196          // ceil(50000/256)

// Scratch (device globals: no runtime allocation allowed)
__device__ __align__(16) float g_xw1[N_NODES * 64];   // x@W1[:64]+b1
__device__ __align__(16) float g_agg[N_NODES * 64];   // per-node sum of relu(h)
__device__ __align__(16) float g_wc[64 * 64];         // W2 @ W3[64:128,:]
__device__ float g_bc[64];                            // b2 @ W3[64:128,:]
__device__ int g_cnt[N_NODES];
__device__ int g_base[N_NODES];
__device__ int g_cursor[N_NODES];
__device__ int g_psrc[N_EDGES];                       // src, dst-sorted
__device__ int g_pe[N_EDGES];                         // edge id, dst-sorted
__device__ int g_pdst[N_EDGES];                       // dst, dst-sorted
__device__ int g_bsum[NB_SCAN];
__device__ int g_boff[256];

typedef unsigned long long u64;

__device__ __forceinline__ u64 pack2(float v) {
    u64 r; asm("mov.b64 %0, {%1, %1};" : "=l"(r) : "f"(v)); return r;
}
__device__ __forceinline__ u64 pack2f(float lo, float hi) {
    u64 r; asm("mov.b64 %0, {%1, %2};" : "=l"(r) : "f"(lo), "f"(hi)); return r;
}
__device__ __forceinline__ void unpack2(u64 v, float &lo, float &hi) {
    asm("mov.b64 {%0, %1}, %2;" : "=f"(lo), "=f"(hi) : "l"(v));
}
__device__ __forceinline__ void ffma2(u64 &d, u64 a, u64 b) {
    asm("fma.rn.f32x2 %0, %1, %2, %0;" : "+l"(d) : "l"(a), "l"(b));
}
__device__ __forceinline__ void red_add_v2(float* addr, float vx, float vy) {
    asm volatile("red.global.add.v2.f32 [%0], {%1, %2};"
                 :: "l"(addr), "f"(vx), "f"(vy) : "memory");
}

// ---------------------------------------------------------------------------
// K0: Wc = W2 @ W3[64:128,:],  bc = b2 @ W3[64:128,:]
// ---------------------------------------------------------------------------
__global__ void __launch_bounds__(64) prep_kernel(
        const float* __restrict__ W2,
        const float* __restrict__ W3,
        const float* __restrict__ b2) {
    __shared__ float sw2[64];
    int i = blockIdx.x, j = threadIdx.x;
    sw2[j] = W2[i * 64 + j];
    __syncthreads();
    float acc = 0.0f;
    #pragma unroll 8
    for (int k = 0; k < 64; k++)
        acc = fmaf(sw2[k], W3[(64 + k) * 64 + j], acc);
    g_wc[i * 64 + j] = acc;
    if (i == 0) {
        float accb = 0.0f;
        for (int k = 0; k < 64; k++)
            accb = fmaf(b2[k], W3[(64 + k) * 64 + j], accb);
        g_bc[j] = accb;
    }
}

// ---------------------------------------------------------------------------
// K1: g_xw1[n] = x[n] @ W1[0:64,:] + b1 ; zero g_agg row, g_cnt.
// ---------------------------------------------------------------------------
__global__ void __launch_bounds__(128) precompute_kernel(
        const float* __restrict__ x,
        const float* __restrict__ W1,
        const float* __restrict__ b1) {
    __shared__ ulonglong2 sW[64 * 16];   // 16 KB
    __shared__ ulonglong2 sb[16];
    int tid = threadIdx.x;
    const ulonglong2* W1v = reinterpret_cast<const ulonglong2*>(W1);
    for (int idx = tid; idx < 64 * 16; idx += 128) sW[idx] = W1v[idx];
    if (tid < 16) sb[tid] = reinterpret_cast<const ulonglong2*>(b1)[tid];
    __syncthreads();

    int n = blockIdx.x * 128 + tid;
    if (n >= N_NODES) return;

    u64 acc[32];
    #pragma unroll
    for (int j = 0; j < 16; j++) { ulonglong2 v = sb[j]; acc[2*j] = v.x; acc[2*j+1] = v.y; }

    const float4* xr = reinterpret_cast<const float4*>(x + (size_t)n * 64);
    #pragma unroll 1
    for (int c = 0; c < 2; c++) {
        float v[32];
        #pragma unroll
        for (int j = 0; j < 8; j++) {
            float4 f = xr[c * 8 + j];
            v[4*j] = f.x; v[4*j+1] = f.y; v[4*j+2] = f.z; v[4*j+3] = f.w;
        }
        #pragma unroll
        for (int i = 0; i < 32; i++) {
            u64 a = pack2(v[i]);
            #pragma unroll
            for (int j = 0; j < 16; j++) {
                ulonglong2 w = sW[(c * 32 + i) * 16 + j];
                ffma2(acc[2*j], a, w.x);
                ffma2(acc[2*j+1], a, w.y);
            }
        }
    }
    ulonglong2* o = reinterpret_cast<ulonglong2*>(g_xw1 + (size_t)n * 64);
    float4* az = reinterpret_cast<float4*>(g_agg + (size_t)n * 64);
    float4 z = make_float4(0.f, 0.f, 0.f, 0.f);
    #pragma unroll
    for (int j = 0; j < 16; j++) {
        ulonglong2 v; v.x = acc[2*j]; v.y = acc[2*j+1]; o[j] = v;
        az[j] = z;
    }
    g_cnt[n] = 0;
}

// ---------------------------------------------------------------------------
// K2: count in-degrees
// ---------------------------------------------------------------------------
__global__ void __launch_bounds__(256) count_kernel(const int* __restrict__ ei) {
    int e = blockIdx.x * 256 + threadIdx.x;
    atomicAdd(&g_cnt[ei[N_EDGES + e]], 1);
}

// ---------------------------------------------------------------------------
// K3a/b/c: two-level parallel exclusive scan of g_cnt -> g_base, g_cursor
// ---------------------------------------------------------------------------
__global__ void __launch_bounds__(256) scanA_kernel() {
    int b = blockIdx.x, tid = threadIdx.x;
    int idx = b * 256 + tid;
    int v = (idx < N_NODES) ? g_cnt[idx] : 0;
    __shared__ int ws[8];
    #pragma unroll
    for (int o = 16; o > 0; o >>= 1) v += __shfl_down_sync(0xffffffffu, v, o);
    if ((tid & 31) == 0) ws[tid >> 5] = v;
    __syncthreads();
    if (tid == 0) {
        int s = 0;
        #pragma unroll
        for (int k = 0; k < 8; k++) s += ws[k];
        g_bsum[b] = s;
    }
}

__global__ void __launch_bounds__(256) scanB_kernel() {
    int tid = threadIdx.x, lane = tid & 31, w = tid >> 5;
    int v = (tid < NB_SCAN) ? g_bsum[tid] : 0;
    int inc = v;
    __shared__ int ws[8];
    #pragma unroll
    for (int o = 1; o < 32; o <<= 1) {
        int t = __shfl_up_sync(0xffffffffu, inc, o);
        if (lane >= o) inc += t;
    }
    if (lane == 31) ws[w] = inc;
    __syncthreads();
    int off = 0;
    #pragma unroll
    for (int k = 0; k < 8; k++) off += (k < w) ? ws[k] : 0;
    g_boff[tid] = off + inc - v;   // exclusive
}

__global__ void __launch_bounds__(256) scanC_kernel() {
    int b = blockIdx.x, tid = threadIdx.x, lane = tid & 31, w = tid >> 5;
    int idx = b * 256 + tid;
    int c = (idx < N_NODES) ? g_cnt[idx] : 0;
    int inc = c;
    __shared__ int ws[8];
    #pragma unroll
    for (int o = 1; o < 32; o <<= 1) {
        int t = __shfl_up_sync(0xffffffffu, inc, o);
        if (lane >= o) inc += t;
    }
    if (lane == 31) ws[w] = inc;
    __syncthreads();
    int off = g_boff[b];
    #pragma unroll
    for (int k = 0; k < 8; k++) off += (k < w) ? ws[k] : 0;
    int base = off + inc - c;
    if (idx < N_NODES) { g_base[idx] = base; g_cursor[idx] = base; }
}

// ---------------------------------------------------------------------------
// K4: place edges into dst-sorted buckets
// ---------------------------------------------------------------------------
__global__ void __launch_bounds__(256) place_kernel(const int* __restrict__ ei) {
    int e = blockIdx.x * 256 + threadIdx.x;
    int d = ei[N_EDGES + e];
    int pos = atomicAdd(&g_cursor[d], 1);
    g_psrc[pos] = ei[e];
    g_pe[pos] = e;
    g_pdst[pos] = d;
}

// ---------------------------------------------------------------------------
// K5: aggregate over sorted slots. Block = 128 slots.
// Phase 0: warp-cooperative staging of xw1[src] rows (coalesced: 2 L1
//          wavefronts/row instead of 32).
// Phase 1: thread reads its own staged row, + ef@W1e, relu, message written
//          back in place.
// Phase 2: warp-chunk reduce (warp-uniform run breaks), red.add.v2.
// ---------------------------------------------------------------------------
__global__ void __launch_bounds__(128) aggregate_kernel(
        const float* __restrict__ ef,
        const float* __restrict__ W1) {
    __shared__ ulonglong2 sW1e[16 * 16];          // 4 KB
    __shared__ float sm[128 * 66];                // 33 KB, stride 66
    __shared__ int sdst[128];

    int tid = threadIdx.x;
    int warp = tid >> 5, lane = tid & 31;
    sW1e[tid * 2]     = reinterpret_cast<const ulonglong2*>(W1)[1024 + tid * 2];
    sW1e[tid * 2 + 1] = reinterpret_cast<const ulonglong2*>(W1)[1024 + tid * 2 + 1];

    int slot = blockIdx.x * 128 + tid;            // N_EDGES % 128 == 0
    int src = g_psrc[slot];
    int e   = g_pe[slot];
    int d   = g_pdst[slot];
    sdst[tid] = d;

    // edge features: per-thread (secondary wavefront cost, issued early)
    float efr[16];
    const float4* er = reinterpret_cast<const float4*>(ef + (size_t)e * 16);
    #pragma unroll
    for (int j = 0; j < 4; j++) {
        float4 f = er[j];
        efr[4*j] = f.x; efr[4*j+1] = f.y; efr[4*j+2] = f.z; efr[4*j+3] = f.w;
    }

    // Phase 0: stage this warp's 32 xw1 rows cooperatively (coalesced LDG.64)
    int s0 = warp * 32;
    #pragma unroll 8
    for (int r = 0; r < 32; r++) {
        int sr = __shfl_sync(0xffffffffu, src, r);
        float2 v = reinterpret_cast<const float2*>(g_xw1 + (size_t)sr * 64)[lane];
        *reinterpret_cast<float2*>(sm + (s0 + r) * 66 + 2 * lane) = v;
    }
    __syncthreads();   // sW1e + staged rows ready

    // Phase 1: own row -> acc, += ef @ W1e, relu, write message in place
    u64 acc[32];
    const float2* myrow = reinterpret_cast<const float2*>(sm + tid * 66);
    #pragma unroll
    for (int j = 0; j < 32; j++) {
        float2 v = myrow[j];
        acc[j] = pack2f(v.x, v.y);
    }
    #pragma unroll
    for (int i = 0; i < 16; i++) {
        u64 a = pack2(efr[i]);
        #pragma unroll
        for (int j = 0; j < 16; j++) {
            ulonglong2 w = sW1e[i * 16 + j];
            ffma2(acc[2*j], a, w.x);
            ffma2(acc[2*j+1], a, w.y);
        }
    }
    float2* myrow_w = reinterpret_cast<float2*>(sm + tid * 66);
    #pragma unroll
    for (int j = 0; j < 32; j++) {
        float lo, hi; unpack2(acc[j], lo, hi);
        myrow_w[j] = make_float2(fmaxf(lo, 0.f), fmaxf(hi, 0.f));
    }
    __syncwarp();      // messages of this warp's chunk visible (all warp-local)

    // Phase 2: warp-chunk reduce over slots [s0, s0+32)
    float sx = 0.0f, sy = 0.0f;
    int dprev = sdst[s0];
    #pragma unroll 4
    for (int t = 0; t < 32; t++) {
        int dcur = sdst[s0 + t];                 // warp-uniform
        if (dcur != dprev) {                     // warp-uniform branch
            red_add_v2(g_agg + (size_t)dprev * 64 + 2 * lane, sx, sy);
            sx = 0.0f; sy = 0.0f;
            dprev = dcur;
        }
        float2 v = *reinterpret_cast<const float2*>(sm + (s0 + t) * 66 + 2 * lane);
        sx += v.x; sy += v.y;
    }
    red_add_v2(g_agg + (size_t)dprev * 64 + 2 * lane, sx, sy);
}

// ---------------------------------------------------------------------------
// K6: fused update+LN (nodeA folded via Wc/bc), M=2 node blocking:
//   acc = x@W3[0:64] + (aggsum*inv)@Wc + b3 + bc*(cnt*inv)
//   y = relu(acc) + x ; LayerNorm -> out
// ---------------------------------------------------------------------------
__global__ void __launch_bounds__(128) nodeB_kernel(
        const float* __restrict__ x,
        const float* __restrict__ W3,
        const float* __restrict__ b3,
        const float* __restrict__ gamma,
        const float* __restrict__ beta,
        float* __restrict__ out) {
    __shared__ ulonglong2 sW[128 * 16];  // 32 KB: rows 0..63 W3 top, 64..127 Wc
    __shared__ float sb3[64], sbc[64], sg[64], sbt[64];
    int tid = threadIdx.x;
    const ulonglong2* W3v = reinterpret_cast<const ulonglong2*>(W3);
    const ulonglong2* Wcv = reinterpret_cast<const ulonglong2*>(g_wc);
    for (int idx = tid; idx < 64 * 16; idx += 128) {
        sW[idx] = W3v[idx];
        sW[64 * 16 + idx] = Wcv[idx];
    }
    if (tid < 64) { sb3[tid] = b3[tid]; sbc[tid] = g_bc[tid]; sg[tid] = gamma[tid]; sbt[tid] = beta[tid]; }
    __syncthreads();

    int n0 = blockIdx.x * 256 + tid;
    int n1 = n0 + 128;
    bool vA = (n0 < N_NODES), vB = (n1 < N_NODES);
    int nA = vA ? n0 : 0, nB = vB ? n1 : 0;

    float cntA = (float)g_cnt[nA];
    float cntB = (float)g_cnt[nB];
    float invA = 1.0f / (cntA + 1e-8f), invB = 1.0f / (cntB + 1e-8f);
    float bsA = cntA * invA, bsB = cntB * invB;

    u64 accA[32], accB[32];
    #pragma unroll
    for (int j = 0; j < 32; j++) {
        accA[j] = pack2f(fmaf(bsA, sbc[2*j], sb3[2*j]), fmaf(bsA, sbc[2*j+1], sb3[2*j+1]));
        accB[j] = pack2f(fmaf(bsB, sbc[2*j], sb3[2*j]), fmaf(bsB, sbc[2*j+1], sb3[2*j+1]));
    }

    const float4* xA = reinterpret_cast<const float4*>(x + (size_t)nA * 64);
    const float4* xB = reinterpret_cast<const float4*>(x + (size_t)nB * 64);
    const float4* aA = reinterpret_cast<const float4*>(g_agg + (size_t)nA * 64);
    const float4* aB = reinterpret_cast<const float4*>(g_agg + (size_t)nB * 64);

    #pragma unroll 1
    for (int c = 0; c < 8; c++) {
        bool isx = (c < 4);
        const float4* pA = isx ? (xA + c * 4) : (aA + (c - 4) * 4);
        const float4* pB = isx ? (xB + c * 4) : (aB + (c - 4) * 4);
        float va[16], vb[16];
        #pragma unroll
        for (int j = 0; j < 4; j++) {
            float4 fa = pA[j];
            float4 fb = pB[j];
            va[4*j] = fa.x; va[4*j+1] = fa.y; va[4*j+2] = fa.z; va[4*j+3] = fa.w;
            vb[4*j] = fb.x; vb[4*j+1] = fb.y; vb[4*j+2] = fb.z; vb[4*j+3] = fb.w;
        }
        if (!isx) {
            #pragma unroll
            for (int j = 0; j < 16; j++) { va[j] *= invA; vb[j] *= invB; }
        }
        #pragma unroll
        for (int i = 0; i < 16; i++) {
            u64 a0 = pack2(va[i]);
            u64 a1 = pack2(vb[i]);
            #pragma unroll
            for (int j = 0; j < 16; j++) {
                ulonglong2 w = sW[(c * 16 + i) * 16 + j];
                ffma2(accA[2*j], a0, w.x); ffma2(accA[2*j+1], a0, w.y);
                ffma2(accB[2*j], a1, w.x); ffma2(accB[2*j+1], a1, w.y);
            }
        }
    }

    // finalize node A then node B (reuse registers)
    #pragma unroll 1
    for (int m = 0; m < 2; m++) {
        bool valid = m ? vB : vA;
        if (!valid) continue;
        int n = m ? n1 : n0;
        u64* acc = m ? accB : accA;
        const float4* xr = reinterpret_cast<const float4*>(x + (size_t)n * 64);

        float u[64];
        #pragma unroll
        for (int j = 0; j < 16; j++) {
            float4 f = xr[j];
            float a0, a1, a2, a3;
            unpack2(acc[2*j],   a0, a1);
            unpack2(acc[2*j+1], a2, a3);
            u[4*j]   = fmaxf(a0, 0.0f) + f.x;
            u[4*j+1] = fmaxf(a1, 0.0f) + f.y;
            u[4*j+2] = fmaxf(a2, 0.0f) + f.z;
            u[4*j+3] = fmaxf(a3, 0.0f) + f.w;
        }
        float s = 0.0f, ss = 0.0f;
        #pragma unroll
        for (int j = 0; j < 64; j++) { s += u[j]; ss = fmaf(u[j], u[j], ss); }
        float mu  = s * (1.0f / 64.0f);
        float var = ss * (1.0f / 64.0f) - mu * mu;
        float r   = rsqrtf(var + 1e-5f);

        float4* o = reinterpret_cast<float4*>(out + (size_t)n * 64);
        #pragma unroll
        for (int j = 0; j < 16; j++) {
            float4 v;
            v.x = (u[4*j]   - mu) * r * sg[4*j]   + sbt[4*j];
            v.y = (u[4*j+1] - mu) * r * sg[4*j+1] + sbt[4*j+1];
            v.z = (u[4*j+2] - mu) * r * sg[4*j+2] + sbt[4*j+2];
            v.w = (u[4*j+3] - mu) * r * sg[4*j+3] + sbt[4*j+3];
            o[j] = v;
        }
    }
}

// ---------------------------------------------------------------------------
extern "C" void kernel_launch(void* const* d_in, const int* in_sizes, int n_in,
                              void* d_out, int out_size) {
    const float* x     = (const float*)d_in[0];
    const int*   ei    = (const int*)  d_in[1];
    const float* ef    = (const float*)d_in[2];
    const float* W1    = (const float*)d_in[3];
    const float* b1    = (const float*)d_in[4];
    const float* W2    = (const float*)d_in[5];
    const float* b2    = (const float*)d_in[6];
    const float* W3    = (const float*)d_in[7];
    const float* b3    = (const float*)d_in[8];
    const float* gamma = (const float*)d_in[9];
    const float* beta  = (const float*)d_in[10];
    float* out = (float*)d_out;

    (void)in_sizes; (void)n_in; (void)out_size;

    const int nb128 = (N_NODES + 127) / 128;
    const int nb256 = (N_NODES + 255) / 256;

    prep_kernel<<<64, 64>>>(W2, W3, b2);
    precompute_kernel<<<nb128, 128>>>(x, W1, b1);
    count_kernel<<<N_EDGES / 256, 256>>>(ei);
    scanA_kernel<<<NB_SCAN, 256>>>();
    scanB_kernel<<<1, 256>>>();
    scanC_kernel<<<NB_SCAN, 256>>>();
    place_kernel<<<N_EDGES / 256, 256>>>(ei);
    aggregate_kernel<<<N_EDGES / 128, 128>>>(ef, W1);
    nodeB_kernel<<<nb256, 128>>>(x, W3, b3, gamma, beta, out);
}

// round 12
// speedup vs baseline: 1.4562x; 1.0637x over previous
#include <cuda_runtime.h>
#include <cstdint>
#include <cstddef>

#define N_NODES 50000
#define N_EDGES 800000
#define NB_SCAN 196          // ceil(50000/256)
#define PC_BLOCKS 391        // ceil(50000/128)  precompute role
#define CNT_BLOCKS 3125      // 800000/256       count role
#define PREP_BLOCKS 64       // prep role

// Scratch (device globals; zero-initialized at module load).
// INVARIANT: g_cnt and g_agg are all-zero at every kernel_launch entry
// (established by load-time zero-init, re-established by nodeB's tail).
__device__ __align__(16) float g_xw1[N_NODES * 64];   // x@W1[:64]+b1
__device__ __align__(16) float g_agg[N_NODES * 64];   // per-node sum of relu(h)
__device__ __align__(16) float g_wc[64 * 64];         // W2 @ W3[64:128,:]
__device__ float g_bc[64];                            // b2 @ W3[64:128,:]
__device__ int g_cnt[N_NODES];
__device__ int g_base[N_NODES];
__device__ int g_cursor[N_NODES];
__device__ int g_psrc[N_EDGES];                       // src, dst-sorted
__device__ int g_pe[N_EDGES];                         // edge id, dst-sorted
__device__ int g_pdst[N_EDGES];                       // dst, dst-sorted
__device__ int g_bsum[NB_SCAN];
__device__ int g_boff[256];

typedef unsigned long long u64;

__device__ __forceinline__ u64 pack2(float v) {
    u64 r; asm("mov.b64 %0, {%1, %1};" : "=l"(r) : "f"(v)); return r;
}
__device__ __forceinline__ u64 pack2f(float lo, float hi) {
    u64 r; asm("mov.b64 %0, {%1, %2};" : "=l"(r) : "f"(lo), "f"(hi)); return r;
}
__device__ __forceinline__ void unpack2(u64 v, float &lo, float &hi) {
    asm("mov.b64 {%0, %1}, %2;" : "=f"(lo), "=f"(hi) : "l"(v));
}
__device__ __forceinline__ void ffma2(u64 &d, u64 a, u64 b) {
    asm("fma.rn.f32x2 %0, %1, %2, %0;" : "+l"(d) : "l"(a), "l"(b));
}
__device__ __forceinline__ void red_add_v2(float* addr, float vx, float vy) {
    asm volatile("red.global.add.v2.f32 [%0], {%1, %2};"
                 :: "l"(addr), "f"(vx), "f"(vy) : "memory");
}

// ---------------------------------------------------------------------------
// K1 (fused): block-role kernel.
//   blocks [0, PC_BLOCKS):              precompute  g_xw1 = x@W1[:64]+b1
//   blocks [PC_BLOCKS, +CNT_BLOCKS):    count in-degrees (g_cnt zero at entry)
//   blocks [.., +PREP_BLOCKS):          prep Wc = W2@W3bot, bc = b2@W3bot
// ---------------------------------------------------------------------------
__global__ void __launch_bounds__(128) fusedA_kernel(
        const float* __restrict__ x,
        const float* __restrict__ W1,
        const float* __restrict__ b1,
        const int*   __restrict__ ei,
        const float* __restrict__ W2,
        const float* __restrict__ W3,
        const float* __restrict__ b2) {
    __shared__ ulonglong2 sW[64 * 16];   // 16 KB (precompute role)
    __shared__ ulonglong2 sb[16];
    __shared__ float sw2[64];            // prep role
    int b = blockIdx.x;
    int tid = threadIdx.x;

    if (b < PC_BLOCKS) {
        // ---- precompute role ----
        const ulonglong2* W1v = reinterpret_cast<const ulonglong2*>(W1);
        for (int idx = tid; idx < 64 * 16; idx += 128) sW[idx] = W1v[idx];
        if (tid < 16) sb[tid] = reinterpret_cast<const ulonglong2*>(b1)[tid];
        __syncthreads();

        int n = b * 128 + tid;
        if (n >= N_NODES) return;

        u64 acc[32];
        #pragma unroll
        for (int j = 0; j < 16; j++) { ulonglong2 v = sb[j]; acc[2*j] = v.x; acc[2*j+1] = v.y; }

        const float4* xr = reinterpret_cast<const float4*>(x + (size_t)n * 64);
        #pragma unroll 1
        for (int c = 0; c < 2; c++) {
            float v[32];
            #pragma unroll
            for (int j = 0; j < 8; j++) {
                float4 f = xr[c * 8 + j];
                v[4*j] = f.x; v[4*j+1] = f.y; v[4*j+2] = f.z; v[4*j+3] = f.w;
            }
            #pragma unroll
            for (int i = 0; i < 32; i++) {
                u64 a = pack2(v[i]);
                #pragma unroll
                for (int j = 0; j < 16; j++) {
                    ulonglong2 w = sW[(c * 32 + i) * 16 + j];
                    ffma2(acc[2*j], a, w.x);
                    ffma2(acc[2*j+1], a, w.y);
                }
            }
        }
        ulonglong2* o = reinterpret_cast<ulonglong2*>(g_xw1 + (size_t)n * 64);
        #pragma unroll
        for (int j = 0; j < 16; j++) {
            ulonglong2 v; v.x = acc[2*j]; v.y = acc[2*j+1]; o[j] = v;
        }
    } else if (b < PC_BLOCKS + CNT_BLOCKS) {
        // ---- count role (256 edges per block) ----
        int e = (b - PC_BLOCKS) * 256 + tid;
        atomicAdd(&g_cnt[ei[N_EDGES + e]], 1);
        atomicAdd(&g_cnt[ei[N_EDGES + e + 128]], 1);
    } else {
        // ---- prep role ----
        int i = b - (PC_BLOCKS + CNT_BLOCKS);
        int j = tid;
        if (j < 64) sw2[j] = W2[i * 64 + j];
        __syncthreads();
        if (j < 64) {
            float acc = 0.0f;
            #pragma unroll 8
            for (int k = 0; k < 64; k++)
                acc = fmaf(sw2[k], W3[(64 + k) * 64 + j], acc);
            g_wc[i * 64 + j] = acc;
            if (i == 0) {
                float accb = 0.0f;
                for (int k = 0; k < 64; k++)
                    accb = fmaf(b2[k], W3[(64 + k) * 64 + j], accb);
                g_bc[j] = accb;
            }
        }
    }
}

// ---------------------------------------------------------------------------
// K3a/b/c: two-level parallel exclusive scan of g_cnt -> g_base, g_cursor
// ---------------------------------------------------------------------------
__global__ void __launch_bounds__(256) scanA_kernel() {
    int b = blockIdx.x, tid = threadIdx.x;
    int idx = b * 256 + tid;
    int v = (idx < N_NODES) ? g_cnt[idx] : 0;
    __shared__ int ws[8];
    #pragma unroll
    for (int o = 16; o > 0; o >>= 1) v += __shfl_down_sync(0xffffffffu, v, o);
    if ((tid & 31) == 0) ws[tid >> 5] = v;
    __syncthreads();
    if (tid == 0) {
        int s = 0;
        #pragma unroll
        for (int k = 0; k < 8; k++) s += ws[k];
        g_bsum[b] = s;
    }
}

__global__ void __launch_bounds__(256) scanB_kernel() {
    int tid = threadIdx.x, lane = tid & 31, w = tid >> 5;
    int v = (tid < NB_SCAN) ? g_bsum[tid] : 0;
    int inc = v;
    __shared__ int ws[8];
    #pragma unroll
    for (int o = 1; o < 32; o <<= 1) {
        int t = __shfl_up_sync(0xffffffffu, inc, o);
        if (lane >= o) inc += t;
    }
    if (lane == 31) ws[w] = inc;
    __syncthreads();
    int off = 0;
    #pragma unroll
    for (int k = 0; k < 8; k++) off += (k < w) ? ws[k] : 0;
    g_boff[tid] = off + inc - v;   // exclusive
}

__global__ void __launch_bounds__(256) scanC_kernel() {
    int b = blockIdx.x, tid = threadIdx.x, lane = tid & 31, w = tid >> 5;
    int idx = b * 256 + tid;
    int c = (idx < N_NODES) ? g_cnt[idx] : 0;
    int inc = c;
    __shared__ int ws[8];
    #pragma unroll
    for (int o = 1; o < 32; o <<= 1) {
        int t = __shfl_up_sync(0xffffffffu, inc, o);
        if (lane >= o) inc += t;
    }
    if (lane == 31) ws[w] = inc;
    __syncthreads();
    int off = g_boff[b];
    #pragma unroll
    for (int k = 0; k < 8; k++) off += (k < w) ? ws[k] : 0;
    int base = off + inc - c;
    if (idx < N_NODES) { g_base[idx] = base; g_cursor[idx] = base; }
}

// ---------------------------------------------------------------------------
// K4: place edges into dst-sorted buckets
// ---------------------------------------------------------------------------
__global__ void __launch_bounds__(256) place_kernel(const int* __restrict__ ei) {
    int e = blockIdx.x * 256 + threadIdx.x;
    int d = ei[N_EDGES + e];
    int pos = atomicAdd(&g_cursor[d], 1);
    g_psrc[pos] = ei[e];
    g_pe[pos] = e;
    g_pdst[pos] = d;
}

// ---------------------------------------------------------------------------
// K5: aggregate over sorted slots. Block = 128 slots.
// Phase a: cooperative ef staging through sm rows (32 wf/warp vs 128).
// Phase b: ef -> regs.
// Phase c: cooperative xw1 staging (round-11 winner).
// Phase d: message compute in place; Phase e: warp-chunk reduce.
// ---------------------------------------------------------------------------
__global__ void __launch_bounds__(128) aggregate_kernel(
        const float* __restrict__ ef,
        const float* __restrict__ W1) {
    __shared__ ulonglong2 sW1e[16 * 16];          // 4 KB
    __shared__ float sm[128 * 66];                // 33 KB, stride 66
    __shared__ int sdst[128];

    int tid = threadIdx.x;
    int warp = tid >> 5, lane = tid & 31;
    sW1e[tid * 2]     = reinterpret_cast<const ulonglong2*>(W1)[1024 + tid * 2];
    sW1e[tid * 2 + 1] = reinterpret_cast<const ulonglong2*>(W1)[1024 + tid * 2 + 1];

    int slot = blockIdx.x * 128 + tid;            // N_EDGES % 128 == 0
    int src = g_psrc[slot];
    int e   = g_pe[slot];
    int d   = g_pdst[slot];
    sdst[tid] = d;

    int s0 = warp * 32;

    // Phase a: cooperative ef staging (4 lanes per row, float4 each)
    #pragma unroll
    for (int it = 0; it < 4; it++) {
        int r = (lane >> 2) + 8 * it;            // row within warp chunk
        int q = lane & 3;
        int eid = __shfl_sync(0xffffffffu, e, r);
        float4 f = *reinterpret_cast<const float4*>(ef + (size_t)eid * 16 + q * 4);
        float* dst = sm + (s0 + r) * 66 + q * 4;
        dst[0] = f.x; dst[1] = f.y; dst[2] = f.z; dst[3] = f.w;
    }
    __syncwarp();

    // Phase b: own ef row -> registers
    float efr[16];
    {
        const float2* mef = reinterpret_cast<const float2*>(sm + tid * 66);
        #pragma unroll
        for (int m = 0; m < 8; m++) {
            float2 v = mef[m];
            efr[2*m] = v.x; efr[2*m+1] = v.y;
        }
    }
    __syncwarp();

    // Phase c: cooperative xw1 staging (coalesced LDG.64)
    #pragma unroll 8
    for (int r = 0; r < 32; r++) {
        int sr = __shfl_sync(0xffffffffu, src, r);
        float2 v = reinterpret_cast<const float2*>(g_xw1 + (size_t)sr * 64)[lane];
        *reinterpret_cast<float2*>(sm + (s0 + r) * 66 + 2 * lane) = v;
    }
    __syncthreads();   // sW1e + staged rows ready

    // Phase d: own row -> acc, += ef @ W1e, relu, write message in place
    u64 acc[32];
    const float2* myrow = reinterpret_cast<const float2*>(sm + tid * 66);
    #pragma unroll
    for (int j = 0; j < 32; j++) {
        float2 v = myrow[j];
        acc[j] = pack2f(v.x, v.y);
    }
    #pragma unroll
    for (int i = 0; i < 16; i++) {
        u64 a = pack2(efr[i]);
        #pragma unroll
        for (int j = 0; j < 16; j++) {
            ulonglong2 w = sW1e[i * 16 + j];
            ffma2(acc[2*j], a, w.x);
            ffma2(acc[2*j+1], a, w.y);
        }
    }
    float2* myrow_w = reinterpret_cast<float2*>(sm + tid * 66);
    #pragma unroll
    for (int j = 0; j < 32; j++) {
        float lo, hi; unpack2(acc[j], lo, hi);
        myrow_w[j] = make_float2(fmaxf(lo, 0.f), fmaxf(hi, 0.f));
    }
    __syncwarp();      // warp-local messages visible

    // Phase e: warp-chunk reduce over slots [s0, s0+32)
    float sx = 0.0f, sy = 0.0f;
    int dprev = sdst[s0];
    #pragma unroll 4
    for (int t = 0; t < 32; t++) {
        int dcur = sdst[s0 + t];                 // warp-uniform
        if (dcur != dprev) {                     // warp-uniform branch
            red_add_v2(g_agg + (size_t)dprev * 64 + 2 * lane, sx, sy);
            sx = 0.0f; sy = 0.0f;
            dprev = dcur;
        }
        float2 v = *reinterpret_cast<const float2*>(sm + (s0 + t) * 66 + 2 * lane);
        sx += v.x; sy += v.y;
    }
    red_add_v2(g_agg + (size_t)dprev * 64 + 2 * lane, sx, sy);
}

// ---------------------------------------------------------------------------
// K6: fused update+LN (nodeA folded via Wc/bc), M=2 node blocking.
// Tail: re-zero g_cnt / g_agg rows (re-establishes the entry invariant).
// ---------------------------------------------------------------------------
__global__ void __launch_bounds__(128) nodeB_kernel(
        const float* __restrict__ x,
        const float* __restrict__ W3,
        const float* __restrict__ b3,
        const float* __restrict__ gamma,
        const float* __restrict__ beta,
        float* __restrict__ out) {
    __shared__ ulonglong2 sW[128 * 16];  // 32 KB: rows 0..63 W3 top, 64..127 Wc
    __shared__ float sb3[64], sbc[64], sg[64], sbt[64];
    int tid = threadIdx.x;
    const ulonglong2* W3v = reinterpret_cast<const ulonglong2*>(W3);
    const ulonglong2* Wcv = reinterpret_cast<const ulonglong2*>(g_wc);
    for (int idx = tid; idx < 64 * 16; idx += 128) {
        sW[idx] = W3v[idx];
        sW[64 * 16 + idx] = Wcv[idx];
    }
    if (tid < 64) { sb3[tid] = b3[tid]; sbc[tid] = g_bc[tid]; sg[tid] = gamma[tid]; sbt[tid] = beta[tid]; }
    __syncthreads();

    int n0 = blockIdx.x * 256 + tid;
    int n1 = n0 + 128;
    bool vA = (n0 < N_NODES), vB = (n1 < N_NODES);
    int nA = vA ? n0 : 0, nB = vB ? n1 : 0;

    float cntA = (float)g_cnt[nA];
    float cntB = (float)g_cnt[nB];
    float invA = 1.0f / (cntA + 1e-8f), invB = 1.0f / (cntB + 1e-8f);
    float bsA = cntA * invA, bsB = cntB * invB;

    u64 accA[32], accB[32];
    #pragma unroll
    for (int j = 0; j < 32; j++) {
        accA[j] = pack2f(fmaf(bsA, sbc[2*j], sb3[2*j]), fmaf(bsA, sbc[2*j+1], sb3[2*j+1]));
        accB[j] = pack2f(fmaf(bsB, sbc[2*j], sb3[2*j]), fmaf(bsB, sbc[2*j+1], sb3[2*j+1]));
    }

    const float4* xA = reinterpret_cast<const float4*>(x + (size_t)nA * 64);
    const float4* xB = reinterpret_cast<const float4*>(x + (size_t)nB * 64);
    const float4* aA = reinterpret_cast<const float4*>(g_agg + (size_t)nA * 64);
    const float4* aB = reinterpret_cast<const float4*>(g_agg + (size_t)nB * 64);

    #pragma unroll 1
    for (int c = 0; c < 8; c++) {
        bool isx = (c < 4);
        const float4* pA = isx ? (xA + c * 4) : (aA + (c - 4) * 4);
        const float4* pB = isx ? (xB + c * 4) : (aB + (c - 4) * 4);
        float va[16], vb[16];
        #pragma unroll
        for (int j = 0; j < 4; j++) {
            float4 fa = pA[j];
            float4 fb = pB[j];
            va[4*j] = fa.x; va[4*j+1] = fa.y; va[4*j+2] = fa.z; va[4*j+3] = fa.w;
            vb[4*j] = fb.x; vb[4*j+1] = fb.y; vb[4*j+2] = fb.z; vb[4*j+3] = fb.w;
        }
        if (!isx) {
            #pragma unroll
            for (int j = 0; j < 16; j++) { va[j] *= invA; vb[j] *= invB; }
        }
        #pragma unroll
        for (int i = 0; i < 16; i++) {
            u64 a0 = pack2(va[i]);
            u64 a1 = pack2(vb[i]);
            #pragma unroll
            for (int j = 0; j < 16; j++) {
                ulonglong2 w = sW[(c * 16 + i) * 16 + j];
                ffma2(accA[2*j], a0, w.x); ffma2(accA[2*j+1], a0, w.y);
                ffma2(accB[2*j], a1, w.x); ffma2(accB[2*j+1], a1, w.y);
            }
        }
    }

    // finalize node A then node B (reuse registers); re-zero scratch
    float4 z = make_float4(0.f, 0.f, 0.f, 0.f);
    #pragma unroll 1
    for (int m = 0; m < 2; m++) {
        bool valid = m ? vB : vA;
        if (!valid) continue;
        int n = m ? n1 : n0;
        u64* acc = m ? accB : accA;
        const float4* xr = reinterpret_cast<const float4*>(x + (size_t)n * 64);

        float u[64];
        #pragma unroll
        for (int j = 0; j < 16; j++) {
            float4 f = xr[j];
            float a0, a1, a2, a3;
            unpack2(acc[2*j],   a0, a1);
            unpack2(acc[2*j+1], a2, a3);
            u[4*j]   = fmaxf(a0, 0.0f) + f.x;
            u[4*j+1] = fmaxf(a1, 0.0f) + f.y;
            u[4*j+2] = fmaxf(a2, 0.0f) + f.z;
            u[4*j+3] = fmaxf(a3, 0.0f) + f.w;
        }
        float s = 0.0f, ss = 0.0f;
        #pragma unroll
        for (int j = 0; j < 64; j++) { s += u[j]; ss = fmaf(u[j], u[j], ss); }
        float mu  = s * (1.0f / 64.0f);
        float var = ss * (1.0f / 64.0f) - mu * mu;
        float r   = rsqrtf(var + 1e-5f);

        float4* o = reinterpret_cast<float4*>(out + (size_t)n * 64);
        float4* az = reinterpret_cast<float4*>(g_agg + (size_t)n * 64);
        #pragma unroll
        for (int j = 0; j < 16; j++) {
            float4 v;
            v.x = (u[4*j]   - mu) * r * sg[4*j]   + sbt[4*j];
            v.y = (u[4*j+1] - mu) * r * sg[4*j+1] + sbt[4*j+1];
            v.z = (u[4*j+2] - mu) * r * sg[4*j+2] + sbt[4*j+2];
            v.w = (u[4*j+3] - mu) * r * sg[4*j+3] + sbt[4*j+3];
            o[j] = v;
            az[j] = z;
        }
        g_cnt[n] = 0;
    }
}

// ---------------------------------------------------------------------------
extern "C" void kernel_launch(void* const* d_in, const int* in_sizes, int n_in,
                              void* d_out, int out_size) {
    const float* x     = (const float*)d_in[0];
    const int*   ei    = (const int*)  d_in[1];
    const float* ef    = (const float*)d_in[2];
    const float* W1    = (const float*)d_in[3];
    const float* b1    = (const float*)d_in[4];
    const float* W2    = (const float*)d_in[5];
    const float* b2    = (const float*)d_in[6];
    const float* W3    = (const float*)d_in[7];
    const float* b3    = (const float*)d_in[8];
    const float* gamma = (const float*)d_in[9];
    const float* beta  = (const float*)d_in[10];
    float* out = (float*)d_out;

    (void)in_sizes; (void)n_in; (void)out_size;

    const int nb256 = (N_NODES + 255) / 256;

    fusedA_kernel<<<PC_BLOCKS + CNT_BLOCKS + PREP_BLOCKS, 128>>>(
        x, W1, b1, ei, W2, W3, b2);
    scanA_kernel<<<NB_SCAN, 256>>>();
    scanB_kernel<<<1, 256>>>();
    scanC_kernel<<<NB_SCAN, 256>>>();
    place_kernel<<<N_EDGES / 256, 256>>>(ei);
    aggregate_kernel<<<N_EDGES / 128, 128>>>(ef, W1);
    nodeB_kernel<<<nb256, 128>>>(x, W3, b3, gamma, beta, out);
}